// round 15
// baseline (speedup 1.0000x reference)
#include <cuda_runtime.h>
#include <math.h>

#define TT 4096
#define EE 512
#define HH 512

// ---------------- scratch (static device globals; no allocation) ----------------
__device__ float g_e[TT];
__device__ float g_xpf[(size_t)TT * 1536];
__device__ float g_xpb[(size_t)TT * 1536];
__device__ float g_out[(size_t)TT * 1024];     // [t][2H]  (fwd 0..511, bwd 512..1023)
__device__ float g_logits[TT];

// ---------------- helpers ----------------
__device__ __forceinline__ float htanh(float x) {      // HW tanh: single MUFU op
    float y;
    asm("tanh.approx.f32 %0, %1;" : "=f"(y) : "f"(x));
    return y;
}
__device__ __forceinline__ unsigned smem_u32(const void* p) {
    unsigned a;
    asm("{ .reg .u64 t; cvta.to.shared.u64 t, %1; cvt.u32.u64 %0, t; }" : "=r"(a) : "l"(p));
    return a;
}
__device__ __forceinline__ unsigned long long lds_vol_u64(unsigned a) {
    unsigned long long v;
    asm volatile("ld.volatile.shared.u64 %0, [%1];" : "=l"(v) : "r"(a));
    return v;
}
__device__ __forceinline__ void fma2(unsigned long long& acc, unsigned long long a,
                                     unsigned long long b) {
    asm("fma.rn.f32x2 %0, %1, %2, %0;" : "+l"(acc) : "l"(a), "l"(b));
}
__device__ __forceinline__ unsigned tf32_rna(float x) {
    unsigned u;
    asm("cvt.rna.tf32.f32 %0, %1;" : "=r"(u) : "f"(x));
    return u;
}
__device__ __forceinline__ void mma_tf32(float c[4], const unsigned a[4], const unsigned b[2]) {
    asm volatile("mma.sync.aligned.m16n8k8.row.col.f32.tf32.tf32.f32 "
                 "{%0,%1,%2,%3}, {%4,%5,%6,%7}, {%8,%9}, {%0,%1,%2,%3};"
                 : "+f"(c[0]), "+f"(c[1]), "+f"(c[2]), "+f"(c[3])
                 : "r"(a[0]), "r"(a[1]), "r"(a[2]), "r"(a[3]), "r"(b[0]), "r"(b[1]));
}

// ---------------- e[t] = dot(query[t], fc_w) + fc_b  (split into 2 launches) ----
__global__ void k_e(const float* __restrict__ q, const float* __restrict__ fcw,
                    const float* __restrict__ fcb, int t0) {
    int t = t0 + blockIdx.x * 8 + (threadIdx.x >> 5);
    int l = threadIdx.x & 31;
    const float* row = q + (size_t)t * EE;
    float s = 0.f;
    #pragma unroll
    for (int i = 0; i < 16; i++) s += row[l + 32 * i] * fcw[l + 32 * i];
    #pragma unroll
    for (int o = 16; o; o >>= 1) s += __shfl_down_sync(0xffffffffu, s, o);
    if (l == 0) g_e[t] = s + fcb[0];
}

// tiny filler launch: puts k_gemm_tf32 in the profiled (4th) slot. Deterministic,
// g_logits is fully overwritten later by k_logits.
__global__ void k_pad() { g_logits[threadIdx.x] = 0.f; }

// ---------------- energy: zero fill WITH fused diagonal (after the GRU) ----------
__global__ void k_zero(float* __restrict__ out, int n4) {
    float4* p = (float4*)(out + 1024);
    int stride = gridDim.x * blockDim.x;
    for (int i = blockIdx.x * blockDim.x + threadIdx.x; i < n4; i += stride) {
        float4 z = make_float4(0.f, 0.f, 0.f, 0.f);
        unsigned base = 4u * (unsigned)i;
        unsigned d = (base + 4096u) / 4097u;
        unsigned pos = d * 4097u;
        if (d < 4096u && pos < base + 4u) ((float*)&z)[pos - base] = g_e[d];
        p[i] = z;
    }
}

// ---------------- GEMM via 3xtf32 mma, hi/lo interleaved as float2 in smem ----------------
// Co[t][n] = sum_k (e[t]*A[t][k]) * W[n][k] + bias[n]
// CTA 256 thr = 8 warps (2m x 4n); CTA tile M=128 N=64; K-tile 16.
// smem stores {hi, lo} float2 pairs -> every fragment load is ONE LDS.64 fetching both
// split halves (fragment-load instruction count halved vs R14).
__global__ void __launch_bounds__(256) k_gemm_tf32(const float* __restrict__ A,
                                                   const float* __restrict__ Wf,
                                                   const float* __restrict__ bf,
                                                   const float* __restrict__ Wb,
                                                   const float* __restrict__ bbp) {
    int which = blockIdx.z;
    const float* __restrict__ W = which ? Wb : Wf;
    const float* __restrict__ bias = which ? bbp : bf;
    float* __restrict__ Co = which ? g_xpb : g_xpf;

    __shared__ float2 Asm[128][17];   // [row][k] {hi,lo}, pitch 17 float2
    __shared__ float2 Bsm[64][17];

    int tid = threadIdx.x;
    int m0 = blockIdx.y * 128, n0 = blockIdx.x * 64;
    int warp = tid >> 5, l = tid & 31;
    int wm = warp >> 2, wn = warp & 3;
    int gr = l >> 2, gc = l & 3;
    int mb = wm * 64, nb = wn * 16;

    // loader roles
    int ar = tid >> 1;            // 0..127
    int ac = (tid & 1) * 8;       // 0 or 8
    int wr = tid >> 2;            // 0..63
    int wc = (tid & 3) * 4;       // 0,4,8,12
    float ea = g_e[m0 + ar];
    const float* pa = A + (size_t)(m0 + ar) * EE + ac;
    const float* pw = W + (size_t)(n0 + wr) * EE + wc;

    float c[4][2][4];
    #pragma unroll
    for (int mi = 0; mi < 4; mi++)
        #pragma unroll
        for (int ni = 0; ni < 2; ni++)
            #pragma unroll
            for (int q = 0; q < 4; q++) c[mi][ni][q] = 0.f;

    // prologue: K-tile 0 into regs
    float4 ra0 = *(const float4*)(pa);
    float4 ra1 = *(const float4*)(pa + 4);
    float4 rw  = *(const float4*)(pw);

    for (int kt = 0; kt < 32; kt++) {
        __syncthreads();   // previous compute done with smem
        {
            float av[8] = {ra0.x, ra0.y, ra0.z, ra0.w, ra1.x, ra1.y, ra1.z, ra1.w};
            #pragma unroll
            for (int i = 0; i < 8; i++) {
                float x = av[i] * ea;
                float fh = __uint_as_float(tf32_rna(x));
                Asm[ar][ac + i] = make_float2(fh, x - fh);
            }
            float wv[4] = {rw.x, rw.y, rw.z, rw.w};
            #pragma unroll
            for (int i = 0; i < 4; i++) {
                float x = wv[i];
                float fh = __uint_as_float(tf32_rna(x));
                Bsm[wr][wc + i] = make_float2(fh, x - fh);
            }
        }
        __syncthreads();
        if (kt + 1 < 32) {     // prefetch next K-tile
            ra0 = *(const float4*)(pa + (kt + 1) * 16);
            ra1 = *(const float4*)(pa + (kt + 1) * 16 + 4);
            rw  = *(const float4*)(pw + (kt + 1) * 16);
        }
        #pragma unroll
        for (int ks = 0; ks < 16; ks += 8) {
            // B fragments: one LDS.64 per element position delivers hi+lo together
            unsigned bh[2][2], bl[2][2];
            #pragma unroll
            for (int ni = 0; ni < 2; ni++) {
                int cn = nb + ni * 8 + gr;
                float2 q0 = Bsm[cn][ks + gc];
                float2 q1 = Bsm[cn][ks + gc + 4];
                bh[ni][0] = __float_as_uint(q0.x); bh[ni][1] = __float_as_uint(q1.x);
                bl[ni][0] = __float_as_uint(q0.y); bl[ni][1] = __float_as_uint(q1.y);
            }
            #pragma unroll
            for (int mi = 0; mi < 4; mi++) {
                int r0 = mb + mi * 16 + gr;
                float2 p00 = Asm[r0][ks + gc];
                float2 p10 = Asm[r0 + 8][ks + gc];
                float2 p01 = Asm[r0][ks + gc + 4];
                float2 p11 = Asm[r0 + 8][ks + gc + 4];
                unsigned ah[4] = {__float_as_uint(p00.x), __float_as_uint(p10.x),
                                  __float_as_uint(p01.x), __float_as_uint(p11.x)};
                unsigned al_[4] = {__float_as_uint(p00.y), __float_as_uint(p10.y),
                                   __float_as_uint(p01.y), __float_as_uint(p11.y)};
                #pragma unroll
                for (int ni = 0; ni < 2; ni++) {
                    mma_tf32(c[mi][ni], ah, bh[ni]);   // hi*hi
                    mma_tf32(c[mi][ni], ah, bl[ni]);   // hi*lo
                    mma_tf32(c[mi][ni], al_, bh[ni]);  // lo*hi
                }
            }
        }
    }
    // epilogue: bias + store (c0/c1 and c2/c3 are col-adjacent -> float2 stores)
    #pragma unroll
    for (int mi = 0; mi < 4; mi++) {
        int row = m0 + mb + mi * 16 + gr;
        #pragma unroll
        for (int ni = 0; ni < 2; ni++) {
            int colb = n0 + nb + ni * 8 + gc * 2;
            float2 bv = *(const float2*)(bias + colb);
            float2 v0 = make_float2(c[mi][ni][0] + bv.x, c[mi][ni][1] + bv.y);
            float2 v1 = make_float2(c[mi][ni][2] + bv.x, c[mi][ni][3] + bv.y);
            *(float2*)(Co + (size_t)row * 1536 + colb) = v0;
            *(float2*)(Co + (size_t)(row + 8) * 1536 + colb) = v1;
        }
    }
}

// ---------------- cluster GRU: R13 winner VERBATIM (two barriers, HW-tanh gates) ----------
__global__ void __launch_bounds__(512, 1) __cluster_dims__(16, 1, 1)
k_gruc(const float* __restrict__ whhf, const float* __restrict__ bhhf,
       const float* __restrict__ whhb, const float* __restrict__ bhhb) {
    __shared__ unsigned long long tagbuf[2][HH];  // [parity][h]: hi=tag, lo=float bits
    __shared__ float hs[HH];

    int dir = blockIdx.x >> 4;
    unsigned rank = blockIdx.x & 15;
    const float* whh = dir ? whhb : whhf;
    const float* bhh = dir ? bhhb : bhhf;
    const float* xp  = dir ? g_xpb : g_xpf;

    int tid = threadIdx.x;
    int w = tid >> 5, l = tid & 31;
    int hw = l >> 4, l2 = l & 15;
    int j = (int)rank * 32 + 2 * w + hw;   // this half-warp's global h index

    tagbuf[0][tid] = 0ull;                     // tag 0, h=0 (state before step 0)
    tagbuf[1][tid] = 0xFFFFFFFF00000000ull;    // invalid
    __syncthreads();
    asm volatile("barrier.cluster.arrive.aligned;" ::: "memory");
    asm volatile("barrier.cluster.wait.aligned;" ::: "memory");

    unsigned long long wr[3][16];
    #pragma unroll
    for (int g = 0; g < 3; g++) {
        const float* row = whh + (size_t)(g * 512 + j) * 512;
        #pragma unroll
        for (int c = 0; c < 8; c++) {
            ulonglong2 v = *(const ulonglong2*)(row + c * 64 + l2 * 4);
            wr[g][c * 2 + 0] = v.x;
            wr[g][c * 2 + 1] = v.y;
        }
    }
    float bh0 = bhh[j], bh1 = bhh[512 + j], bh2 = bhh[1024 + j];
    float hold = 0.f;

    unsigned tb_base = smem_u32(&tagbuf[0][0]);

    float xr_c, xz_c, xn_c;
    {
        const float* row0 = xp + (size_t)(dir ? (TT - 1) : 0) * 1536;
        xr_c = (__ldg(row0 + j) + bh0) * 0.5f;
        xz_c = (__ldg(row0 + 512 + j) + bh1) * 0.5f;
        xn_c = __ldg(row0 + 1024 + j);
    }

    for (int t = 0; t < TT; t++) {
        int tn = (t + 1 < TT) ? (t + 1) : t;
        const float* xprow = xp + (size_t)(dir ? (TT - 1 - tn) : tn) * 1536;
        float xr_n = __ldg(xprow + j);
        float xz_n = __ldg(xprow + 512 + j);
        float xn_n = __ldg(xprow + 1024 + j);

        unsigned slot = tb_base + ((t & 1) ? 4096u : 0u) + (unsigned)tid * 8u;
        unsigned tg = (unsigned)t;
        unsigned long long v = lds_vol_u64(slot);
        while ((unsigned)(v >> 32) != tg) v = lds_vol_u64(slot);
        hs[tid] = __uint_as_float((unsigned)v);
        __syncthreads();

        unsigned long long a0p = 0ull, a1p = 0ull, a2p = 0ull;
        const ulonglong2* hp = (const ulonglong2*)hs;
        #pragma unroll
        for (int c = 0; c < 8; c++) {
            ulonglong2 hv = hp[(c * 64 + l2 * 4) >> 2];
            fma2(a0p, wr[0][c*2+0], hv.x); fma2(a0p, wr[0][c*2+1], hv.y);
            fma2(a1p, wr[1][c*2+0], hv.x); fma2(a1p, wr[1][c*2+1], hv.y);
            fma2(a2p, wr[2][c*2+0], hv.x); fma2(a2p, wr[2][c*2+1], hv.y);
        }
        float a0 = __uint_as_float((unsigned)a0p) + __uint_as_float((unsigned)(a0p >> 32));
        float a1 = __uint_as_float((unsigned)a1p) + __uint_as_float((unsigned)(a1p >> 32));
        float a2 = __uint_as_float((unsigned)a2p) + __uint_as_float((unsigned)(a2p >> 32));
        #pragma unroll
        for (int o = 8; o; o >>= 1) {
            a0 += __shfl_xor_sync(0xffffffffu, a0, o, 16);
            a1 += __shfl_xor_sync(0xffffffffu, a1, o, 16);
            a2 += __shfl_xor_sync(0xffffffffu, a2, o, 16);
        }
        float r = __fmaf_rn(0.5f, htanh(__fmaf_rn(0.5f, a0, xr_c)), 0.5f);
        float z = __fmaf_rn(0.5f, htanh(__fmaf_rn(0.5f, a1, xz_c)), 0.5f);
        float n = htanh(__fmaf_rn(r, a2 + bh2, xn_c));
        float hnew = __fmaf_rn(z, hold - n, n);   // (1-z)*n + z*h
        hold = hnew;
        if (t + 1 < TT) {
            unsigned long long pv = ((unsigned long long)(unsigned)(t + 1) << 32) |
                                    (unsigned long long)__float_as_uint(hnew);
            unsigned loff = tb_base + (((t + 1) & 1) ? 4096u : 0u) + (unsigned)j * 8u;
            unsigned raddr;
            asm("mapa.shared::cluster.u32 %0, %1, %2;"
                : "=r"(raddr) : "r"(loff), "r"((unsigned)l2));
            asm volatile("st.shared::cluster.u64 [%0], %1;"
                         :: "r"(raddr), "l"(pv) : "memory");
        }
        if (l2 == 0) {
            int orow = dir ? (TT - 1 - t) : t;
            g_out[(size_t)orow * 1024 + dir * 512 + j] = hnew;
        }
        xr_c = (xr_n + bh0) * 0.5f;
        xz_c = (xz_n + bh1) * 0.5f;
        xn_c = xn_n;
        __syncthreads();
    }
    asm volatile("barrier.cluster.arrive.aligned;" ::: "memory");
    asm volatile("barrier.cluster.wait.aligned;" ::: "memory");
}

// ---------------- attention epilogue (fused) ----------------
__global__ void k_logits() {
    __shared__ float hid[1024];
    int tid = threadIdx.x;   // 256
    for (int i = tid; i < 512; i += 256) {
        hid[i] = g_out[512 + i];                              // hb_last
        hid[512 + i] = g_out[(size_t)4095 * 1024 + i];        // hf_last
    }
    __syncthreads();
    int t = blockIdx.x * 8 + (tid >> 5);
    int l = tid & 31;
    const float* row = g_out + (size_t)t * 1024;
    float s = 0.f;
    #pragma unroll
    for (int i = 0; i < 32; i++) s += row[l + 32 * i] * hid[l + 32 * i];
    #pragma unroll
    for (int o = 16; o; o >>= 1) s += __shfl_down_sync(0xffffffffu, s, o);
    if (l == 0) g_logits[t] = s * 0.03125f;  // 1/sqrt(1024)
}

__global__ void k_lin(float* __restrict__ out) {
    __shared__ float redm[8], reds[8];
    __shared__ float sm[4][64];
    int tid = threadIdx.x;   // 256
    float m = -1e30f;
    for (int i = tid; i < TT; i += 256) m = fmaxf(m, g_logits[i]);
    #pragma unroll
    for (int o = 16; o; o >>= 1) m = fmaxf(m, __shfl_xor_sync(0xffffffffu, m, o));
    if ((tid & 31) == 0) redm[tid >> 5] = m;
    __syncthreads();
    if (tid < 32) {
        float v = (tid < 8) ? redm[tid] : -1e30f;
        #pragma unroll
        for (int o = 4; o; o >>= 1) v = fmaxf(v, __shfl_xor_sync(0xffffffffu, v, o));
        if (tid == 0) redm[0] = v;
    }
    __syncthreads();
    m = redm[0];
    float s = 0.f;
    for (int i = tid; i < TT; i += 256) s += __expf(g_logits[i] - m);
    #pragma unroll
    for (int o = 16; o; o >>= 1) s += __shfl_xor_sync(0xffffffffu, s, o);
    if ((tid & 31) == 0) reds[tid >> 5] = s;
    __syncthreads();
    if (tid < 32) {
        float v = (tid < 8) ? reds[tid] : 0.f;
        #pragma unroll
        for (int o = 4; o; o >>= 1) v += __shfl_xor_sync(0xffffffffu, v, o);
        if (tid == 0) reds[0] = v;
    }
    __syncthreads();
    float inv = __fdividef(1.f, reds[0]);
    int c = blockIdx.x;
    int jj = tid & 63;
    int rr = tid >> 6;
    int col = c * 64 + jj;
    float acc = 0.f;
    for (int t = rr; t < TT; t += 4)
        acc += __expf(g_logits[t] - m) * g_out[(size_t)t * 1024 + col];
    sm[rr][jj] = acc;
    __syncthreads();
    if (rr == 0) out[col] = (sm[0][jj] + sm[1][jj] + sm[2][jj] + sm[3][jj]) * inv;
}

// ---------------- launch ----------------
extern "C" void kernel_launch(void* const* d_in, const int* in_sizes, int n_in,
                              void* d_out, int out_size) {
    const float* input = (const float*)d_in[0];
    const float* query = (const float*)d_in[1];
    const float* fc_w  = (const float*)d_in[2];
    const float* fc_b  = (const float*)d_in[3];
    const float* wihf  = (const float*)d_in[4];
    const float* whhf  = (const float*)d_in[5];
    const float* bihf  = (const float*)d_in[6];
    const float* bhhf  = (const float*)d_in[7];
    const float* wihb  = (const float*)d_in[8];
    const float* whhb  = (const float*)d_in[9];
    const float* bihb  = (const float*)d_in[10];
    const float* bhhb  = (const float*)d_in[11];
    float* out = (float*)d_out;

    int n4 = (out_size - 1024) / 4;  // energy float4 count

    cudaFuncSetAttribute(k_gruc, cudaFuncAttributeNonPortableClusterSizeAllowed, 1);

    // k_e x2 + pad so k_gemm_tf32 lands in the profiled (4th) slot
    k_e<<<TT / 16, 256>>>(query, fc_w, fc_b, 0);
    k_e<<<TT / 16, 256>>>(query, fc_w, fc_b, TT / 2);
    k_pad<<<1, 256>>>();
    dim3 gg(1536 / 64, TT / 128, 2);
    k_gemm_tf32<<<gg, 256>>>(input, wihf, bihf, wihb, bihb);   // 4th -> ncu target
    k_gruc<<<32, 512>>>(whhf, bhhf, whhb, bhhb);
    k_zero<<<4096, 256>>>(out, n4);
    k_logits<<<TT / 8, 256>>>();
    k_lin<<<16, 256>>>(out);
}

// round 16
// speedup vs baseline: 1.0246x; 1.0246x over previous
#include <cuda_runtime.h>
#include <math.h>

#define TT 4096
#define EE 512
#define HH 512

// ---------------- scratch (static device globals; no allocation) ----------------
__device__ float g_e[TT];
__device__ float g_xpf[(size_t)TT * 1536];
__device__ float g_xpb[(size_t)TT * 1536];
__device__ float g_out[(size_t)TT * 1024];     // [t][2H]  (fwd 0..511, bwd 512..1023)
__device__ float g_logits[TT];

// ---------------- helpers ----------------
__device__ __forceinline__ float htanh(float x) {      // HW tanh: single MUFU op
    float y;
    asm("tanh.approx.f32 %0, %1;" : "=f"(y) : "f"(x));
    return y;
}
__device__ __forceinline__ unsigned smem_u32(const void* p) {
    unsigned a;
    asm("{ .reg .u64 t; cvta.to.shared.u64 t, %1; cvt.u32.u64 %0, t; }" : "=r"(a) : "l"(p));
    return a;
}
__device__ __forceinline__ unsigned long long lds_vol_u64(unsigned a) {
    unsigned long long v;
    asm volatile("ld.volatile.shared.u64 %0, [%1];" : "=l"(v) : "r"(a));
    return v;
}
__device__ __forceinline__ void fma2(unsigned long long& acc, unsigned long long a,
                                     unsigned long long b) {
    asm("fma.rn.f32x2 %0, %1, %2, %0;" : "+l"(acc) : "l"(a), "l"(b));
}
__device__ __forceinline__ unsigned tf32_rna(float x) {
    unsigned u;
    asm("cvt.rna.tf32.f32 %0, %1;" : "=r"(u) : "f"(x));
    return u;
}
__device__ __forceinline__ void mma_tf32(float c[4], const unsigned a[4], const unsigned b[2]) {
    asm volatile("mma.sync.aligned.m16n8k8.row.col.f32.tf32.tf32.f32 "
                 "{%0,%1,%2,%3}, {%4,%5,%6,%7}, {%8,%9}, {%0,%1,%2,%3};"
                 : "+f"(c[0]), "+f"(c[1]), "+f"(c[2]), "+f"(c[3])
                 : "r"(a[0]), "r"(a[1]), "r"(a[2]), "r"(a[3]), "r"(b[0]), "r"(b[1]));
}

// ---------------- e[t] = dot(query[t], fc_w) + fc_b  (split into 2 launches) ----
__global__ void k_e(const float* __restrict__ q, const float* __restrict__ fcw,
                    const float* __restrict__ fcb, int t0) {
    int t = t0 + blockIdx.x * 8 + (threadIdx.x >> 5);
    int l = threadIdx.x & 31;
    const float* row = q + (size_t)t * EE;
    float s = 0.f;
    #pragma unroll
    for (int i = 0; i < 16; i++) s += row[l + 32 * i] * fcw[l + 32 * i];
    #pragma unroll
    for (int o = 16; o; o >>= 1) s += __shfl_down_sync(0xffffffffu, s, o);
    if (l == 0) g_e[t] = s + fcb[0];
}

// tiny filler: keeps k_gemm_tf32 in the profiled (4th) slot
__global__ void k_pad() { g_logits[threadIdx.x] = 0.f; }

// ---------------- energy: zero fill WITH fused diagonal (after the GRU) ----------
__global__ void k_zero(float* __restrict__ out, int n4) {
    float4* p = (float4*)(out + 1024);
    int stride = gridDim.x * blockDim.x;
    for (int i = blockIdx.x * blockDim.x + threadIdx.x; i < n4; i += stride) {
        float4 z = make_float4(0.f, 0.f, 0.f, 0.f);
        unsigned base = 4u * (unsigned)i;
        unsigned d = (base + 4096u) / 4097u;
        unsigned pos = d * 4097u;
        if (d < 4096u && pos < base + 4u) ((float*)&z)[pos - base] = g_e[d];
        p[i] = z;
    }
}

// ---------------- GEMM via 3xtf32 mma, R14 conflict-free layout + smem DOUBLE BUFFER -------
// Co[t][n] = sum_k (e[t]*A[t][k]) * W[n][k] + bias[n]
// CTA 256 thr = 8 warps (2m x 4n); CTA tile M=128 N=64; K-tile 16; ONE barrier per K-tile.
// smem layout per buffer: Ah[16][136], Al[16][136], Bh[16][72], Bl[16][72]  (scalar,
// fragment-load bank = 8*gc + gr spans 0..31 -> conflict-free).
// Pipeline: mma(buf p) overlaps convert->buf p^1 (tile kt+1 from regs) and LDG of kt+2.
#define A_PLANE 2176   // 16*136
#define B_PLANE 1152   // 16*72
#define BUF_FLOATS (2 * A_PLANE + 2 * B_PLANE)      // 6656 floats = 26624 B
#define GEMM_SMEM (2 * BUF_FLOATS * 4)              // 53248 B

__global__ void __launch_bounds__(256) k_gemm_tf32(const float* __restrict__ A,
                                                   const float* __restrict__ Wf,
                                                   const float* __restrict__ bf,
                                                   const float* __restrict__ Wb,
                                                   const float* __restrict__ bbp) {
    extern __shared__ float sm[];
    int which = blockIdx.z;
    const float* __restrict__ W = which ? Wb : Wf;
    const float* __restrict__ bias = which ? bbp : bf;
    float* __restrict__ Co = which ? g_xpb : g_xpf;

    int tid = threadIdx.x;
    int m0 = blockIdx.y * 128, n0 = blockIdx.x * 64;
    int warp = tid >> 5, l = tid & 31;
    int wm = warp >> 2, wn = warp & 3;
    int gr = l >> 2, gc = l & 3;
    int mb = wm * 64, nb = wn * 16;

    // loader roles
    int ar = tid >> 1;            // 0..127
    int ac = (tid & 1) * 8;       // 0 or 8
    int wr = tid >> 2;            // 0..63
    int wc = (tid & 3) * 4;       // 0,4,8,12
    float ea = g_e[m0 + ar];
    const float* pa = A + (size_t)(m0 + ar) * EE + ac;
    const float* pw = W + (size_t)(n0 + wr) * EE + wc;

    float c[4][2][4];
    #pragma unroll
    for (int mi = 0; mi < 4; mi++)
        #pragma unroll
        for (int ni = 0; ni < 2; ni++)
            #pragma unroll
            for (int q = 0; q < 4; q++) c[mi][ni][q] = 0.f;

    // convert-and-store helper targets
    //   Ah = buf; Al = buf+A_PLANE; Bh = buf+2*A_PLANE; Bl = buf+2*A_PLANE+B_PLANE
    #define CONVERT_TILE(buf, va0, va1, vw) do {                                   \
        float* Ah_ = (buf); float* Al_ = (buf) + A_PLANE;                          \
        float* Bh_ = (buf) + 2 * A_PLANE; float* Bl_ = (buf) + 2 * A_PLANE + B_PLANE; \
        float av_[8] = {(va0).x, (va0).y, (va0).z, (va0).w,                        \
                        (va1).x, (va1).y, (va1).z, (va1).w};                       \
        _Pragma("unroll")                                                          \
        for (int i_ = 0; i_ < 8; i_++) {                                           \
            float x_ = av_[i_] * ea;                                               \
            float fh_ = __uint_as_float(tf32_rna(x_));                             \
            Ah_[(ac + i_) * 136 + ar] = fh_;                                       \
            Al_[(ac + i_) * 136 + ar] = x_ - fh_;                                  \
        }                                                                          \
        float wv_[4] = {(vw).x, (vw).y, (vw).z, (vw).w};                           \
        _Pragma("unroll")                                                          \
        for (int i_ = 0; i_ < 4; i_++) {                                           \
            float x_ = wv_[i_];                                                    \
            float fh_ = __uint_as_float(tf32_rna(x_));                             \
            Bh_[(wc + i_) * 72 + wr] = fh_;                                        \
            Bl_[(wc + i_) * 72 + wr] = x_ - fh_;                                   \
        }                                                                          \
    } while (0)

    // prologue: tile 0 -> buf0; then cur regs <- tile 1
    float4 ca0 = *(const float4*)(pa);
    float4 ca1 = *(const float4*)(pa + 4);
    float4 cw  = *(const float4*)(pw);
    CONVERT_TILE(sm, ca0, ca1, cw);
    __syncthreads();
    ca0 = *(const float4*)(pa + 16);
    ca1 = *(const float4*)(pa + 20);
    cw  = *(const float4*)(pw + 16);

    for (int kt = 0; kt < 32; kt++) {
        float* bufp = sm + (kt & 1) * BUF_FLOATS;
        float* bufn = sm + ((kt & 1) ^ 1) * BUF_FLOATS;
        // issue LDG for tile kt+2 early (consumed next iteration's convert)
        float4 na0, na1, nw;
        if (kt < 30) {
            na0 = *(const float4*)(pa + (kt + 2) * 16);
            na1 = *(const float4*)(pa + (kt + 2) * 16 + 4);
            nw  = *(const float4*)(pw + (kt + 2) * 16);
        }
        // mma on buffer p (conflict-free fragment loads)
        {
            const float* Ahp = bufp;
            const float* Alp = bufp + A_PLANE;
            const float* Bhp = bufp + 2 * A_PLANE;
            const float* Blp = bufp + 2 * A_PLANE + B_PLANE;
            #pragma unroll
            for (int ks = 0; ks < 16; ks += 8) {
                unsigned bh[2][2], bl[2][2];
                #pragma unroll
                for (int ni = 0; ni < 2; ni++) {
                    int cn = nb + ni * 8 + gr;
                    bh[ni][0] = __float_as_uint(Bhp[(ks + gc) * 72 + cn]);
                    bh[ni][1] = __float_as_uint(Bhp[(ks + gc + 4) * 72 + cn]);
                    bl[ni][0] = __float_as_uint(Blp[(ks + gc) * 72 + cn]);
                    bl[ni][1] = __float_as_uint(Blp[(ks + gc + 4) * 72 + cn]);
                }
                #pragma unroll
                for (int mi = 0; mi < 4; mi++) {
                    int r0 = mb + mi * 16 + gr;
                    unsigned ah[4], al_[4];
                    ah[0] = __float_as_uint(Ahp[(ks + gc) * 136 + r0]);
                    ah[1] = __float_as_uint(Ahp[(ks + gc) * 136 + r0 + 8]);
                    ah[2] = __float_as_uint(Ahp[(ks + gc + 4) * 136 + r0]);
                    ah[3] = __float_as_uint(Ahp[(ks + gc + 4) * 136 + r0 + 8]);
                    al_[0] = __float_as_uint(Alp[(ks + gc) * 136 + r0]);
                    al_[1] = __float_as_uint(Alp[(ks + gc) * 136 + r0 + 8]);
                    al_[2] = __float_as_uint(Alp[(ks + gc + 4) * 136 + r0]);
                    al_[3] = __float_as_uint(Alp[(ks + gc + 4) * 136 + r0 + 8]);
                    #pragma unroll
                    for (int ni = 0; ni < 2; ni++) {
                        mma_tf32(c[mi][ni], ah, bh[ni]);   // hi*hi
                        mma_tf32(c[mi][ni], ah, bl[ni]);   // hi*lo
                        mma_tf32(c[mi][ni], al_, bh[ni]);  // lo*hi
                    }
                }
            }
        }
        // convert tile kt+1 (in cur regs) into the other buffer; overlaps mma tail
        if (kt < 31) CONVERT_TILE(bufn, ca0, ca1, cw);
        if (kt < 30) { ca0 = na0; ca1 = na1; cw = nw; }
        __syncthreads();   // ONE barrier per K-tile
    }
    #undef CONVERT_TILE

    // epilogue: bias + store (c0/c1 and c2/c3 are col-adjacent -> float2 stores)
    #pragma unroll
    for (int mi = 0; mi < 4; mi++) {
        int row = m0 + mb + mi * 16 + gr;
        #pragma unroll
        for (int ni = 0; ni < 2; ni++) {
            int colb = n0 + nb + ni * 8 + gc * 2;
            float2 bv = *(const float2*)(bias + colb);
            float2 v0 = make_float2(c[mi][ni][0] + bv.x, c[mi][ni][1] + bv.y);
            float2 v1 = make_float2(c[mi][ni][2] + bv.x, c[mi][ni][3] + bv.y);
            *(float2*)(Co + (size_t)row * 1536 + colb) = v0;
            *(float2*)(Co + (size_t)(row + 8) * 1536 + colb) = v1;
        }
    }
}

// ---------------- cluster GRU: R13 winner VERBATIM (two barriers, HW-tanh gates) ----------
__global__ void __launch_bounds__(512, 1) __cluster_dims__(16, 1, 1)
k_gruc(const float* __restrict__ whhf, const float* __restrict__ bhhf,
       const float* __restrict__ whhb, const float* __restrict__ bhhb) {
    __shared__ unsigned long long tagbuf[2][HH];  // [parity][h]: hi=tag, lo=float bits
    __shared__ float hs[HH];

    int dir = blockIdx.x >> 4;
    unsigned rank = blockIdx.x & 15;
    const float* whh = dir ? whhb : whhf;
    const float* bhh = dir ? bhhb : bhhf;
    const float* xp  = dir ? g_xpb : g_xpf;

    int tid = threadIdx.x;
    int w = tid >> 5, l = tid & 31;
    int hw = l >> 4, l2 = l & 15;
    int j = (int)rank * 32 + 2 * w + hw;   // this half-warp's global h index

    tagbuf[0][tid] = 0ull;                     // tag 0, h=0 (state before step 0)
    tagbuf[1][tid] = 0xFFFFFFFF00000000ull;    // invalid
    __syncthreads();
    asm volatile("barrier.cluster.arrive.aligned;" ::: "memory");
    asm volatile("barrier.cluster.wait.aligned;" ::: "memory");

    unsigned long long wr[3][16];
    #pragma unroll
    for (int g = 0; g < 3; g++) {
        const float* row = whh + (size_t)(g * 512 + j) * 512;
        #pragma unroll
        for (int c = 0; c < 8; c++) {
            ulonglong2 v = *(const ulonglong2*)(row + c * 64 + l2 * 4);
            wr[g][c * 2 + 0] = v.x;
            wr[g][c * 2 + 1] = v.y;
        }
    }
    float bh0 = bhh[j], bh1 = bhh[512 + j], bh2 = bhh[1024 + j];
    float hold = 0.f;

    unsigned tb_base = smem_u32(&tagbuf[0][0]);

    float xr_c, xz_c, xn_c;
    {
        const float* row0 = xp + (size_t)(dir ? (TT - 1) : 0) * 1536;
        xr_c = (__ldg(row0 + j) + bh0) * 0.5f;
        xz_c = (__ldg(row0 + 512 + j) + bh1) * 0.5f;
        xn_c = __ldg(row0 + 1024 + j);
    }

    for (int t = 0; t < TT; t++) {
        int tn = (t + 1 < TT) ? (t + 1) : t;
        const float* xprow = xp + (size_t)(dir ? (TT - 1 - tn) : tn) * 1536;
        float xr_n = __ldg(xprow + j);
        float xz_n = __ldg(xprow + 512 + j);
        float xn_n = __ldg(xprow + 1024 + j);

        unsigned slot = tb_base + ((t & 1) ? 4096u : 0u) + (unsigned)tid * 8u;
        unsigned tg = (unsigned)t;
        unsigned long long v = lds_vol_u64(slot);
        while ((unsigned)(v >> 32) != tg) v = lds_vol_u64(slot);
        hs[tid] = __uint_as_float((unsigned)v);
        __syncthreads();

        unsigned long long a0p = 0ull, a1p = 0ull, a2p = 0ull;
        const ulonglong2* hp = (const ulonglong2*)hs;
        #pragma unroll
        for (int c = 0; c < 8; c++) {
            ulonglong2 hv = hp[(c * 64 + l2 * 4) >> 2];
            fma2(a0p, wr[0][c*2+0], hv.x); fma2(a0p, wr[0][c*2+1], hv.y);
            fma2(a1p, wr[1][c*2+0], hv.x); fma2(a1p, wr[1][c*2+1], hv.y);
            fma2(a2p, wr[2][c*2+0], hv.x); fma2(a2p, wr[2][c*2+1], hv.y);
        }
        float a0 = __uint_as_float((unsigned)a0p) + __uint_as_float((unsigned)(a0p >> 32));
        float a1 = __uint_as_float((unsigned)a1p) + __uint_as_float((unsigned)(a1p >> 32));
        float a2 = __uint_as_float((unsigned)a2p) + __uint_as_float((unsigned)(a2p >> 32));
        #pragma unroll
        for (int o = 8; o; o >>= 1) {
            a0 += __shfl_xor_sync(0xffffffffu, a0, o, 16);
            a1 += __shfl_xor_sync(0xffffffffu, a1, o, 16);
            a2 += __shfl_xor_sync(0xffffffffu, a2, o, 16);
        }
        float r = __fmaf_rn(0.5f, htanh(__fmaf_rn(0.5f, a0, xr_c)), 0.5f);
        float z = __fmaf_rn(0.5f, htanh(__fmaf_rn(0.5f, a1, xz_c)), 0.5f);
        float n = htanh(__fmaf_rn(r, a2 + bh2, xn_c));
        float hnew = __fmaf_rn(z, hold - n, n);   // (1-z)*n + z*h
        hold = hnew;
        if (t + 1 < TT) {
            unsigned long long pv = ((unsigned long long)(unsigned)(t + 1) << 32) |
                                    (unsigned long long)__float_as_uint(hnew);
            unsigned loff = tb_base + (((t + 1) & 1) ? 4096u : 0u) + (unsigned)j * 8u;
            unsigned raddr;
            asm("mapa.shared::cluster.u32 %0, %1, %2;"
                : "=r"(raddr) : "r"(loff), "r"((unsigned)l2));
            asm volatile("st.shared::cluster.u64 [%0], %1;"
                         :: "r"(raddr), "l"(pv) : "memory");
        }
        if (l2 == 0) {
            int orow = dir ? (TT - 1 - t) : t;
            g_out[(size_t)orow * 1024 + dir * 512 + j] = hnew;
        }
        xr_c = (xr_n + bh0) * 0.5f;
        xz_c = (xz_n + bh1) * 0.5f;
        xn_c = xn_n;
        __syncthreads();
    }
    asm volatile("barrier.cluster.arrive.aligned;" ::: "memory");
    asm volatile("barrier.cluster.wait.aligned;" ::: "memory");
}

// ---------------- attention epilogue (fused) ----------------
__global__ void k_logits() {
    __shared__ float hid[1024];
    int tid = threadIdx.x;   // 256
    for (int i = tid; i < 512; i += 256) {
        hid[i] = g_out[512 + i];                              // hb_last
        hid[512 + i] = g_out[(size_t)4095 * 1024 + i];        // hf_last
    }
    __syncthreads();
    int t = blockIdx.x * 8 + (tid >> 5);
    int l = tid & 31;
    const float* row = g_out + (size_t)t * 1024;
    float s = 0.f;
    #pragma unroll
    for (int i = 0; i < 32; i++) s += row[l + 32 * i] * hid[l + 32 * i];
    #pragma unroll
    for (int o = 16; o; o >>= 1) s += __shfl_down_sync(0xffffffffu, s, o);
    if (l == 0) g_logits[t] = s * 0.03125f;  // 1/sqrt(1024)
}

__global__ void k_lin(float* __restrict__ out) {
    __shared__ float redm[8], reds[8];
    __shared__ float sm2[4][64];
    int tid = threadIdx.x;   // 256
    float m = -1e30f;
    for (int i = tid; i < TT; i += 256) m = fmaxf(m, g_logits[i]);
    #pragma unroll
    for (int o = 16; o; o >>= 1) m = fmaxf(m, __shfl_xor_sync(0xffffffffu, m, o));
    if ((tid & 31) == 0) redm[tid >> 5] = m;
    __syncthreads();
    if (tid < 32) {
        float v = (tid < 8) ? redm[tid] : -1e30f;
        #pragma unroll
        for (int o = 4; o; o >>= 1) v = fmaxf(v, __shfl_xor_sync(0xffffffffu, v, o));
        if (tid == 0) redm[0] = v;
    }
    __syncthreads();
    m = redm[0];
    float s = 0.f;
    for (int i = tid; i < TT; i += 256) s += __expf(g_logits[i] - m);
    #pragma unroll
    for (int o = 16; o; o >>= 1) s += __shfl_xor_sync(0xffffffffu, s, o);
    if ((tid & 31) == 0) reds[tid >> 5] = s;
    __syncthreads();
    if (tid < 32) {
        float v = (tid < 8) ? reds[tid] : 0.f;
        #pragma unroll
        for (int o = 4; o; o >>= 1) v += __shfl_xor_sync(0xffffffffu, v, o);
        if (tid == 0) reds[0] = v;
    }
    __syncthreads();
    float inv = __fdividef(1.f, reds[0]);
    int c = blockIdx.x;
    int jj = tid & 63;
    int rr = tid >> 6;
    int col = c * 64 + jj;
    float acc = 0.f;
    for (int t = rr; t < TT; t += 4)
        acc += __expf(g_logits[t] - m) * g_out[(size_t)t * 1024 + col];
    sm2[rr][jj] = acc;
    __syncthreads();
    if (rr == 0) out[col] = (sm2[0][jj] + sm2[1][jj] + sm2[2][jj] + sm2[3][jj]) * inv;
}

// ---------------- launch ----------------
extern "C" void kernel_launch(void* const* d_in, const int* in_sizes, int n_in,
                              void* d_out, int out_size) {
    const float* input = (const float*)d_in[0];
    const float* query = (const float*)d_in[1];
    const float* fc_w  = (const float*)d_in[2];
    const float* fc_b  = (const float*)d_in[3];
    const float* wihf  = (const float*)d_in[4];
    const float* whhf  = (const float*)d_in[5];
    const float* bihf  = (const float*)d_in[6];
    const float* bhhf  = (const float*)d_in[7];
    const float* wihb  = (const float*)d_in[8];
    const float* whhb  = (const float*)d_in[9];
    const float* bihb  = (const float*)d_in[10];
    const float* bhhb  = (const float*)d_in[11];
    float* out = (float*)d_out;

    int n4 = (out_size - 1024) / 4;  // energy float4 count

    cudaFuncSetAttribute(k_gruc, cudaFuncAttributeNonPortableClusterSizeAllowed, 1);
    cudaFuncSetAttribute(k_gemm_tf32, cudaFuncAttributeMaxDynamicSharedMemorySize, GEMM_SMEM);

    // k_e x2 + pad so k_gemm_tf32 lands in the profiled (4th) slot
    k_e<<<TT / 16, 256>>>(query, fc_w, fc_b, 0);
    k_e<<<TT / 16, 256>>>(query, fc_w, fc_b, TT / 2);
    k_pad<<<1, 256>>>();
    dim3 gg(1536 / 64, TT / 128, 2);
    k_gemm_tf32<<<gg, 256, GEMM_SMEM>>>(input, wihf, bihf, wihb, bihb);  // 4th -> ncu
    k_gruc<<<32, 512>>>(whhf, bhhf, whhb, bhhb);
    k_zero<<<4096, 256>>>(out, n4);
    k_logits<<<TT / 8, 256>>>();
    k_lin<<<16, 256>>>(out);
}

// round 17
// speedup vs baseline: 1.0601x; 1.0347x over previous
#include <cuda_runtime.h>
#include <math.h>

#define TT 4096
#define EE 512
#define HH 512

// ---------------- scratch (static device globals; no allocation) ----------------
__device__ float g_e[TT];
__device__ float g_xpf[(size_t)TT * 1536];
__device__ float g_xpb[(size_t)TT * 1536];
__device__ float g_out[(size_t)TT * 1024];     // [t][2H]  (fwd 0..511, bwd 512..1023)
__device__ float g_logits[TT];

// ---------------- helpers ----------------
__device__ __forceinline__ float htanh(float x) {      // HW tanh: single MUFU op
    float y;
    asm("tanh.approx.f32 %0, %1;" : "=f"(y) : "f"(x));
    return y;
}
__device__ __forceinline__ unsigned smem_u32(const void* p) {
    unsigned a;
    asm("{ .reg .u64 t; cvta.to.shared.u64 t, %1; cvt.u32.u64 %0, t; }" : "=r"(a) : "l"(p));
    return a;
}
__device__ __forceinline__ unsigned long long lds_vol_u64(unsigned a) {
    unsigned long long v;
    asm volatile("ld.volatile.shared.u64 %0, [%1];" : "=l"(v) : "r"(a));
    return v;
}
__device__ __forceinline__ void fma2(unsigned long long& acc, unsigned long long a,
                                     unsigned long long b) {
    asm("fma.rn.f32x2 %0, %1, %2, %0;" : "+l"(acc) : "l"(a), "l"(b));
}
__device__ __forceinline__ unsigned tf32_rna(float x) {
    unsigned u;
    asm("cvt.rna.tf32.f32 %0, %1;" : "=r"(u) : "f"(x));
    return u;
}
__device__ __forceinline__ void mma_tf32(float c[4], const unsigned a[4], const unsigned b[2]) {
    asm volatile("mma.sync.aligned.m16n8k8.row.col.f32.tf32.tf32.f32 "
                 "{%0,%1,%2,%3}, {%4,%5,%6,%7}, {%8,%9}, {%0,%1,%2,%3};"
                 : "+f"(c[0]), "+f"(c[1]), "+f"(c[2]), "+f"(c[3])
                 : "r"(a[0]), "r"(a[1]), "r"(a[2]), "r"(a[3]), "r"(b[0]), "r"(b[1]));
}

// ---------------- e[t] = dot(query[t], fc_w) + fc_b ----------------
__global__ void k_e(const float* __restrict__ q, const float* __restrict__ fcw,
                    const float* __restrict__ fcb) {
    int t = blockIdx.x * 8 + (threadIdx.x >> 5);
    int l = threadIdx.x & 31;
    const float* row = q + (size_t)t * EE;
    float s = 0.f;
    #pragma unroll
    for (int i = 0; i < 16; i++) s += row[l + 32 * i] * fcw[l + 32 * i];
    #pragma unroll
    for (int o = 16; o; o >>= 1) s += __shfl_down_sync(0xffffffffu, s, o);
    if (l == 0) g_e[t] = s + fcb[0];
}

// ---------------- energy: zero fill WITH fused diagonal (after the GRU) ----------
__global__ void k_zero(float* __restrict__ out, int n4) {
    float4* p = (float4*)(out + 1024);
    int stride = gridDim.x * blockDim.x;
    for (int i = blockIdx.x * blockDim.x + threadIdx.x; i < n4; i += stride) {
        float4 z = make_float4(0.f, 0.f, 0.f, 0.f);
        unsigned base = 4u * (unsigned)i;               // element index in 4096x4096 plane
        unsigned d = (base + 4096u) / 4097u;            // ceil(base/4097)
        unsigned pos = d * 4097u;                       // candidate diagonal element
        if (d < 4096u && pos < base + 4u) ((float*)&z)[pos - base] = g_e[d];
        p[i] = z;
    }
}

// ---------------- GEMM via 3xtf32 mma (R14 winner: conflict-free scalar layout) -----------
// Co[t][n] = sum_k (e[t]*A[t][k]) * W[n][k] + bias[n]
// CTA 256 thr = 8 warps (2m x 4n); CTA tile M=128, N=64; warp tile 64x16; K-tile 16.
// x split hi/lo with cvt.rna.tf32: acc += Ah*Bh + Ah*Bl + Al*Bh  (error ~2^-22).
// smem strides 136/72: fragment-load bank index = 8*gc+gr spans 0..31 (conflict-free).
__global__ void __launch_bounds__(256) k_gemm_tf32(const float* __restrict__ A,
                                                   const float* __restrict__ Wf,
                                                   const float* __restrict__ bf,
                                                   const float* __restrict__ Wb,
                                                   const float* __restrict__ bbp) {
    int which = blockIdx.z;
    const float* __restrict__ W = which ? Wb : Wf;
    const float* __restrict__ bias = which ? bbp : bf;
    float* __restrict__ Co = which ? g_xpb : g_xpf;

    __shared__ float Ah[16][136], Al[16][136];
    __shared__ float Bh[16][72],  Bl[16][72];

    int tid = threadIdx.x;
    int m0 = blockIdx.y * 128, n0 = blockIdx.x * 64;
    int warp = tid >> 5, l = tid & 31;
    int wm = warp >> 2, wn = warp & 3;
    int gr = l >> 2, gc = l & 3;
    int mb = wm * 64, nb = wn * 16;

    // loader roles
    int ar = tid >> 1;            // 0..127
    int ac = (tid & 1) * 8;       // 0 or 8
    int wr = tid >> 2;            // 0..63
    int wc = (tid & 3) * 4;       // 0,4,8,12
    float ea = g_e[m0 + ar];
    const float* pa = A + (size_t)(m0 + ar) * EE + ac;
    const float* pw = W + (size_t)(n0 + wr) * EE + wc;

    float c[4][2][4];
    #pragma unroll
    for (int mi = 0; mi < 4; mi++)
        #pragma unroll
        for (int ni = 0; ni < 2; ni++)
            #pragma unroll
            for (int q = 0; q < 4; q++) c[mi][ni][q] = 0.f;

    // prologue: K-tile 0 into regs
    float4 ra0 = *(const float4*)(pa);
    float4 ra1 = *(const float4*)(pa + 4);
    float4 rw  = *(const float4*)(pw);

    for (int kt = 0; kt < 32; kt++) {
        __syncthreads();   // previous compute done with smem
        {
            float av[8] = {ra0.x, ra0.y, ra0.z, ra0.w, ra1.x, ra1.y, ra1.z, ra1.w};
            #pragma unroll
            for (int i = 0; i < 8; i++) {
                float x = av[i] * ea;
                float fh = __uint_as_float(tf32_rna(x));
                Ah[ac + i][ar] = fh;
                Al[ac + i][ar] = x - fh;
            }
            float wv[4] = {rw.x, rw.y, rw.z, rw.w};
            #pragma unroll
            for (int i = 0; i < 4; i++) {
                float x = wv[i];
                float fh = __uint_as_float(tf32_rna(x));
                Bh[wc + i][wr] = fh;
                Bl[wc + i][wr] = x - fh;
            }
        }
        __syncthreads();
        if (kt + 1 < 32) {     // prefetch next K-tile
            ra0 = *(const float4*)(pa + (kt + 1) * 16);
            ra1 = *(const float4*)(pa + (kt + 1) * 16 + 4);
            rw  = *(const float4*)(pw + (kt + 1) * 16);
        }
        #pragma unroll
        for (int ks = 0; ks < 16; ks += 8) {
            // B fragments for both n8 tiles (hi & lo)
            unsigned bh[2][2], bl[2][2];
            #pragma unroll
            for (int ni = 0; ni < 2; ni++) {
                int cn = nb + ni * 8 + gr;
                bh[ni][0] = __float_as_uint(Bh[ks + gc][cn]);
                bh[ni][1] = __float_as_uint(Bh[ks + gc + 4][cn]);
                bl[ni][0] = __float_as_uint(Bl[ks + gc][cn]);
                bl[ni][1] = __float_as_uint(Bl[ks + gc + 4][cn]);
            }
            #pragma unroll
            for (int mi = 0; mi < 4; mi++) {
                int r0 = mb + mi * 16 + gr;
                unsigned ah[4], al_[4];
                ah[0] = __float_as_uint(Ah[ks + gc][r0]);
                ah[1] = __float_as_uint(Ah[ks + gc][r0 + 8]);
                ah[2] = __float_as_uint(Ah[ks + gc + 4][r0]);
                ah[3] = __float_as_uint(Ah[ks + gc + 4][r0 + 8]);
                al_[0] = __float_as_uint(Al[ks + gc][r0]);
                al_[1] = __float_as_uint(Al[ks + gc][r0 + 8]);
                al_[2] = __float_as_uint(Al[ks + gc + 4][r0]);
                al_[3] = __float_as_uint(Al[ks + gc + 4][r0 + 8]);
                #pragma unroll
                for (int ni = 0; ni < 2; ni++) {
                    mma_tf32(c[mi][ni], ah, bh[ni]);   // hi*hi
                    mma_tf32(c[mi][ni], ah, bl[ni]);   // hi*lo
                    mma_tf32(c[mi][ni], al_, bh[ni]);  // lo*hi
                }
            }
        }
    }
    // epilogue: bias + store (c0/c1 and c2/c3 are col-adjacent -> float2 stores)
    #pragma unroll
    for (int mi = 0; mi < 4; mi++) {
        int row = m0 + mb + mi * 16 + gr;
        #pragma unroll
        for (int ni = 0; ni < 2; ni++) {
            int colb = n0 + nb + ni * 8 + gc * 2;
            float2 bv = *(const float2*)(bias + colb);
            float2 v0 = make_float2(c[mi][ni][0] + bv.x, c[mi][ni][1] + bv.y);
            float2 v1 = make_float2(c[mi][ni][2] + bv.x, c[mi][ni][3] + bv.y);
            *(float2*)(Co + (size_t)row * 1536 + colb) = v0;
            *(float2*)(Co + (size_t)(row + 8) * 1536 + colb) = v1;
        }
    }
}

// ---------------- cluster GRU: R13 winner VERBATIM (two barriers, HW-tanh gates) ----------
__global__ void __launch_bounds__(512, 1) __cluster_dims__(16, 1, 1)
k_gruc(const float* __restrict__ whhf, const float* __restrict__ bhhf,
       const float* __restrict__ whhb, const float* __restrict__ bhhb) {
    __shared__ unsigned long long tagbuf[2][HH];  // [parity][h]: hi=tag, lo=float bits
    __shared__ float hs[HH];

    int dir = blockIdx.x >> 4;
    unsigned rank = blockIdx.x & 15;
    const float* whh = dir ? whhb : whhf;
    const float* bhh = dir ? bhhb : bhhf;
    const float* xp  = dir ? g_xpb : g_xpf;

    int tid = threadIdx.x;
    int w = tid >> 5, l = tid & 31;
    int hw = l >> 4, l2 = l & 15;
    int j = (int)rank * 32 + 2 * w + hw;   // this half-warp's global h index

    tagbuf[0][tid] = 0ull;                     // tag 0, h=0 (state before step 0)
    tagbuf[1][tid] = 0xFFFFFFFF00000000ull;    // invalid
    __syncthreads();
    asm volatile("barrier.cluster.arrive.aligned;" ::: "memory");
    asm volatile("barrier.cluster.wait.aligned;" ::: "memory");

    unsigned long long wr[3][16];
    #pragma unroll
    for (int g = 0; g < 3; g++) {
        const float* row = whh + (size_t)(g * 512 + j) * 512;
        #pragma unroll
        for (int c = 0; c < 8; c++) {
            ulonglong2 v = *(const ulonglong2*)(row + c * 64 + l2 * 4);
            wr[g][c * 2 + 0] = v.x;
            wr[g][c * 2 + 1] = v.y;
        }
    }
    float bh0 = bhh[j], bh1 = bhh[512 + j], bh2 = bhh[1024 + j];
    float hold = 0.f;

    unsigned tb_base = smem_u32(&tagbuf[0][0]);

    float xr_c, xz_c, xn_c;
    {
        const float* row0 = xp + (size_t)(dir ? (TT - 1) : 0) * 1536;
        xr_c = (__ldg(row0 + j) + bh0) * 0.5f;
        xz_c = (__ldg(row0 + 512 + j) + bh1) * 0.5f;
        xn_c = __ldg(row0 + 1024 + j);
    }

    for (int t = 0; t < TT; t++) {
        int tn = (t + 1 < TT) ? (t + 1) : t;
        const float* xprow = xp + (size_t)(dir ? (TT - 1 - tn) : tn) * 1536;
        float xr_n = __ldg(xprow + j);
        float xz_n = __ldg(xprow + 512 + j);
        float xn_n = __ldg(xprow + 1024 + j);

        unsigned slot = tb_base + ((t & 1) ? 4096u : 0u) + (unsigned)tid * 8u;
        unsigned tg = (unsigned)t;
        unsigned long long v = lds_vol_u64(slot);
        while ((unsigned)(v >> 32) != tg) v = lds_vol_u64(slot);
        hs[tid] = __uint_as_float((unsigned)v);
        __syncthreads();

        unsigned long long a0p = 0ull, a1p = 0ull, a2p = 0ull;
        const ulonglong2* hp = (const ulonglong2*)hs;
        #pragma unroll
        for (int c = 0; c < 8; c++) {
            ulonglong2 hv = hp[(c * 64 + l2 * 4) >> 2];
            fma2(a0p, wr[0][c*2+0], hv.x); fma2(a0p, wr[0][c*2+1], hv.y);
            fma2(a1p, wr[1][c*2+0], hv.x); fma2(a1p, wr[1][c*2+1], hv.y);
            fma2(a2p, wr[2][c*2+0], hv.x); fma2(a2p, wr[2][c*2+1], hv.y);
        }
        float a0 = __uint_as_float((unsigned)a0p) + __uint_as_float((unsigned)(a0p >> 32));
        float a1 = __uint_as_float((unsigned)a1p) + __uint_as_float((unsigned)(a1p >> 32));
        float a2 = __uint_as_float((unsigned)a2p) + __uint_as_float((unsigned)(a2p >> 32));
        #pragma unroll
        for (int o = 8; o; o >>= 1) {
            a0 += __shfl_xor_sync(0xffffffffu, a0, o, 16);
            a1 += __shfl_xor_sync(0xffffffffu, a1, o, 16);
            a2 += __shfl_xor_sync(0xffffffffu, a2, o, 16);
        }
        float r = __fmaf_rn(0.5f, htanh(__fmaf_rn(0.5f, a0, xr_c)), 0.5f);
        float z = __fmaf_rn(0.5f, htanh(__fmaf_rn(0.5f, a1, xz_c)), 0.5f);
        float n = htanh(__fmaf_rn(r, a2 + bh2, xn_c));
        float hnew = __fmaf_rn(z, hold - n, n);   // (1-z)*n + z*h
        hold = hnew;
        if (t + 1 < TT) {
            unsigned long long pv = ((unsigned long long)(unsigned)(t + 1) << 32) |
                                    (unsigned long long)__float_as_uint(hnew);
            unsigned loff = tb_base + (((t + 1) & 1) ? 4096u : 0u) + (unsigned)j * 8u;
            unsigned raddr;
            asm("mapa.shared::cluster.u32 %0, %1, %2;"
                : "=r"(raddr) : "r"(loff), "r"((unsigned)l2));
            asm volatile("st.shared::cluster.u64 [%0], %1;"
                         :: "r"(raddr), "l"(pv) : "memory");
        }
        if (l2 == 0) {
            int orow = dir ? (TT - 1 - t) : t;
            g_out[(size_t)orow * 1024 + dir * 512 + j] = hnew;
        }
        xr_c = (xr_n + bh0) * 0.5f;
        xz_c = (xz_n + bh1) * 0.5f;
        xn_c = xn_n;
        __syncthreads();
    }
    asm volatile("barrier.cluster.arrive.aligned;" ::: "memory");
    asm volatile("barrier.cluster.wait.aligned;" ::: "memory");
}

// ---------------- attention epilogue (fused) ----------------
__global__ void k_logits() {
    __shared__ float hid[1024];
    int tid = threadIdx.x;   // 256
    for (int i = tid; i < 512; i += 256) {
        hid[i] = g_out[512 + i];                              // hb_last
        hid[512 + i] = g_out[(size_t)4095 * 1024 + i];        // hf_last
    }
    __syncthreads();
    int t = blockIdx.x * 8 + (tid >> 5);
    int l = tid & 31;
    const float* row = g_out + (size_t)t * 1024;
    float s = 0.f;
    #pragma unroll
    for (int i = 0; i < 32; i++) s += row[l + 32 * i] * hid[l + 32 * i];
    #pragma unroll
    for (int o = 16; o; o >>= 1) s += __shfl_down_sync(0xffffffffu, s, o);
    if (l == 0) g_logits[t] = s * 0.03125f;  // 1/sqrt(1024)
}

__global__ void k_lin(float* __restrict__ out) {
    __shared__ float redm[8], reds[8];
    __shared__ float sm2[4][64];
    int tid = threadIdx.x;   // 256
    float m = -1e30f;
    for (int i = tid; i < TT; i += 256) m = fmaxf(m, g_logits[i]);
    #pragma unroll
    for (int o = 16; o; o >>= 1) m = fmaxf(m, __shfl_xor_sync(0xffffffffu, m, o));
    if ((tid & 31) == 0) redm[tid >> 5] = m;
    __syncthreads();
    if (tid < 32) {
        float v = (tid < 8) ? redm[tid] : -1e30f;
        #pragma unroll
        for (int o = 4; o; o >>= 1) v = fmaxf(v, __shfl_xor_sync(0xffffffffu, v, o));
        if (tid == 0) redm[0] = v;
    }
    __syncthreads();
    m = redm[0];
    float s = 0.f;
    for (int i = tid; i < TT; i += 256) s += __expf(g_logits[i] - m);
    #pragma unroll
    for (int o = 16; o; o >>= 1) s += __shfl_xor_sync(0xffffffffu, s, o);
    if ((tid & 31) == 0) reds[tid >> 5] = s;
    __syncthreads();
    if (tid < 32) {
        float v = (tid < 8) ? reds[tid] : 0.f;
        #pragma unroll
        for (int o = 4; o; o >>= 1) v += __shfl_xor_sync(0xffffffffu, v, o);
        if (tid == 0) reds[0] = v;
    }
    __syncthreads();
    float inv = __fdividef(1.f, reds[0]);
    int c = blockIdx.x;
    int jj = tid & 63;
    int rr = tid >> 6;
    int col = c * 64 + jj;
    float acc = 0.f;
    for (int t = rr; t < TT; t += 4)
        acc += __expf(g_logits[t] - m) * g_out[(size_t)t * 1024 + col];
    sm2[rr][jj] = acc;
    __syncthreads();
    if (rr == 0) out[col] = (sm2[0][jj] + sm2[1][jj] + sm2[2][jj] + sm2[3][jj]) * inv;
}

// ---------------- launch ----------------
extern "C" void kernel_launch(void* const* d_in, const int* in_sizes, int n_in,
                              void* d_out, int out_size) {
    const float* input = (const float*)d_in[0];
    const float* query = (const float*)d_in[1];
    const float* fc_w  = (const float*)d_in[2];
    const float* fc_b  = (const float*)d_in[3];
    const float* wihf  = (const float*)d_in[4];
    const float* whhf  = (const float*)d_in[5];
    const float* bihf  = (const float*)d_in[6];
    const float* bhhf  = (const float*)d_in[7];
    const float* wihb  = (const float*)d_in[8];
    const float* whhb  = (const float*)d_in[9];
    const float* bibb  = (const float*)d_in[10];
    const float* bhhb  = (const float*)d_in[11];
    float* out = (float*)d_out;

    int n4 = (out_size - 1024) / 4;  // energy float4 count

    cudaFuncSetAttribute(k_gruc, cudaFuncAttributeNonPortableClusterSizeAllowed, 1);

    k_e<<<TT / 8, 256>>>(query, fc_w, fc_b);
    dim3 gg(1536 / 64, TT / 128, 2);
    k_gemm_tf32<<<gg, 256>>>(input, wihf, bihf, wihb, bibb);
    k_gruc<<<32, 512>>>(whhf, bhhf, whhb, bhhb);   // GRU owns the chip; xp L2-hot
    k_zero<<<4096, 256>>>(out, n4);                // zero + diagonal fused, after the GRU
    k_logits<<<TT / 8, 256>>>();
    k_lin<<<16, 256>>>(out);
}